// round 5
// baseline (speedup 1.0000x reference)
#include <cuda_runtime.h>
#include <cuda_fp16.h>
#include <cstdint>

#define NP 16384      // number of z vectors (16*32*32)
#define NC 8192       // codebook size
#define DIM 256       // embedding dim
#define DECAYF 0.99f
#define OMDECAYF 0.01f
#define EPSF 1e-5f

// GEMM tiling
#define BM 128
#define BN 128
#define BK 32                  // halves per k-chunk
#define NCHUNK (DIM / BK)      // 8
#define STAGES 3
#define ROWB 80                // smem row stride in bytes (32 halves + 8 pad) -> conflict-free ldmatrix
#define TILE_B (128 * ROWB)    // 10240 bytes per tile
#define STAGE_B (4 * TILE_B)   // A_hi, A_lo, B_hi, B_lo

// ---------------- scratch (no allocation allowed) ----------------
__device__ unsigned long long g_best[NP];   // packed (ordered_score<<32 | idx)
__device__ float g_wnorm[NC];
__device__ float g_counts[NC];
__device__ float g_ptloss[NP];
__device__ float g_n;
__device__ __align__(256) __half g_zh[NP * DIM];
__device__ __align__(256) __half g_zl[NP * DIM];
__device__ __align__(256) __half g_wh[NC * DIM];
__device__ __align__(256) __half g_wl[NC * DIM];

// ---------------- PTX helpers ----------------
__device__ __forceinline__ uint32_t smem_u32(const void* p) {
    uint32_t a;
    asm("{ .reg .u64 t; cvta.to.shared.u64 t, %1; cvt.u32.u64 %0, t; }" : "=r"(a) : "l"(p));
    return a;
}
__device__ __forceinline__ void cp16(uint32_t dst, const void* src) {
    asm volatile("cp.async.cg.shared.global [%0], [%1], 16;" :: "r"(dst), "l"(src) : "memory");
}
#define CP_COMMIT() asm volatile("cp.async.commit_group;" ::: "memory")
#define CP_WAIT1()  asm volatile("cp.async.wait_group 1;" ::: "memory")

__device__ __forceinline__ void ldm_x4(uint32_t* r, uint32_t addr) {
    asm volatile("ldmatrix.sync.aligned.m8n8.x4.shared.b16 {%0,%1,%2,%3}, [%4];"
        : "=r"(r[0]), "=r"(r[1]), "=r"(r[2]), "=r"(r[3]) : "r"(addr));
}
__device__ __forceinline__ void mma16816(float* c, const uint32_t* a, const uint32_t* b) {
    asm volatile(
        "mma.sync.aligned.m16n8k16.row.col.f32.f16.f16.f32 "
        "{%0,%1,%2,%3}, {%4,%5,%6,%7}, {%8,%9}, {%0,%1,%2,%3};"
        : "+f"(c[0]), "+f"(c[1]), "+f"(c[2]), "+f"(c[3])
        : "r"(a[0]), "r"(a[1]), "r"(a[2]), "r"(a[3]), "r"(b[0]), "r"(b[1]));
}

// ---------------- K0: init scratch + out_embed_avg = DECAY*embed_avg ----------------
__global__ void init_kernel(const float* __restrict__ ea_in, float* __restrict__ out_ea) {
    int i = blockIdx.x * blockDim.x + threadIdx.x;
    if (i < NP) g_best[i] = 0xFFFFFFFFFFFFFFFFull;
    if (i < NC) g_counts[i] = 0.f;
    if (i < NC * DIM) out_ea[i] = DECAYF * ea_in[i];
}

// ---------------- K1: fp16 hi/lo split of z and w ----------------
__global__ void split_kernel(const float* __restrict__ z, const float* __restrict__ w) {
    int i = blockIdx.x * blockDim.x + threadIdx.x;
    if (i < NP * DIM) {
        float x = z[i];
        __half h = __float2half_rn(x);
        g_zh[i] = h;
        g_zl[i] = __float2half_rn(x - __half2float(h));
    }
    if (i < NC * DIM) {
        float x = w[i];
        __half h = __float2half_rn(x);
        g_wh[i] = h;
        g_wl[i] = __float2half_rn(x - __half2float(h));
    }
}

// ---------------- K2: per-code squared norms (fp32 exact) ----------------
__global__ void wnorm_kernel(const float* __restrict__ w) {
    int warp = (blockIdx.x * blockDim.x + threadIdx.x) >> 5;
    int lane = threadIdx.x & 31;
    if (warp >= NC) return;
    const float4* row = (const float4*)(w + (size_t)warp * DIM);
    float s = 0.f;
#pragma unroll
    for (int it = 0; it < 2; it++) {
        float4 v = row[lane + it * 32];
        s += v.x * v.x + v.y * v.y + v.z * v.z + v.w * v.w;
    }
#pragma unroll
    for (int off = 16; off; off >>= 1) s += __shfl_xor_sync(0xffffffffu, s, off);
    if (lane == 0) g_wnorm[warp] = s;
}

// ---------------- K3: mma.sync fp16-split GEMM + fused argmin ----------------
// dot = zh*wh + zh*wl + zl*wh ; score = ||w||^2 - 2*dot
// MMAs issued as 3 passes over the 16 independent accumulators -> no RAW stalls.
__global__ __launch_bounds__(256, 1) void mma_gemm_argmin() {
    extern __shared__ char smem[];
    const uint32_t sb = smem_u32(smem);
    const int tid = threadIdx.x, wid = tid >> 5, lane = tid & 31;
    const int warp_m = wid >> 2, warp_n = wid & 3;   // 2 x 4 warps
    const int m0 = blockIdx.x * BM, n0 = blockIdx.y * BN;

    constexpr uint32_t OFF_STAGE = 1024;

    // wnorm tile
    float* wns = (float*)smem;
    if (tid < BN) wns[tid] = g_wnorm[n0 + tid];

    // ---- cp.async stage loader ----
    auto load_stage = [&](int chunk, int stg) {
        const uint32_t stage = sb + OFF_STAGE + stg * STAGE_B;
#pragma unroll
        for (int r = 0; r < 8; r++) {
            int idx = tid + r * 256;           // 0..2047
            int tile = idx >> 9;               // 0..3
            int q = idx & 511;
            int row = q >> 2, cj = q & 3;
            const __half* src;
            if (tile == 0)      src = g_zh + (size_t)(m0 + row) * DIM;
            else if (tile == 1) src = g_zl + (size_t)(m0 + row) * DIM;
            else if (tile == 2) src = g_wh + (size_t)(n0 + row) * DIM;
            else                src = g_wl + (size_t)(n0 + row) * DIM;
            src += chunk * BK + cj * 8;
            cp16(stage + tile * TILE_B + row * ROWB + cj * 16, src);
        }
    };

    load_stage(0, 0); CP_COMMIT();
    load_stage(1, 1); CP_COMMIT();

    float c[4][4][4] = {};    // [mt][nt][4]

    for (int ch = 0; ch < NCHUNK; ch++) {
        CP_WAIT1();
        __syncthreads();
        if (ch + 2 < NCHUNK) load_stage(ch + 2, (ch + 2) % STAGES);
        CP_COMMIT();

        const uint32_t stage = sb + OFF_STAGE + (ch % STAGES) * STAGE_B;
        const uint32_t sAh = stage;
        const uint32_t sAl = stage + TILE_B;
        const uint32_t sBh = stage + 2 * TILE_B;
        const uint32_t sBl = stage + 3 * TILE_B;

#pragma unroll
        for (int s = 0; s < 2; s++) {          // two k16 steps per chunk
            const uint32_t acol = s * 32 + ((lane >> 4) << 4);
            const int arow = lane & 15;
            uint32_t ah[4][4], al[4][4];
#pragma unroll
            for (int mt = 0; mt < 4; mt++) {
                uint32_t off = (uint32_t)(warp_m * 64 + mt * 16 + arow) * ROWB + acol;
                ldm_x4(ah[mt], sAh + off);
                ldm_x4(al[mt], sAl + off);
            }
            const int brow = ((lane >> 4) << 3) + (lane & 7);
            const uint32_t bcol = s * 32 + ((lane >> 3) & 1) * 16;
            uint32_t bh[2][4], bl[2][4];
#pragma unroll
            for (int nt2 = 0; nt2 < 2; nt2++) {
                uint32_t off = (uint32_t)(warp_n * 32 + nt2 * 16 + brow) * ROWB + bcol;
                ldm_x4(bh[nt2], sBh + off);
                ldm_x4(bl[nt2], sBl + off);
            }
            // pass 1: hi*hi over all 16 independent accumulators
#pragma unroll
            for (int mt = 0; mt < 4; mt++)
#pragma unroll
                for (int nt = 0; nt < 4; nt++)
                    mma16816(c[mt][nt], ah[mt], &bh[nt >> 1][(nt & 1) * 2]);
            // pass 2: hi*lo
#pragma unroll
            for (int mt = 0; mt < 4; mt++)
#pragma unroll
                for (int nt = 0; nt < 4; nt++)
                    mma16816(c[mt][nt], ah[mt], &bl[nt >> 1][(nt & 1) * 2]);
            // pass 3: lo*hi
#pragma unroll
            for (int mt = 0; mt < 4; mt++)
#pragma unroll
                for (int nt = 0; nt < 4; nt++)
                    mma16816(c[mt][nt], al[mt], &bh[nt >> 1][(nt & 1) * 2]);
        }
    }

    // ---- epilogue: fused argmin ----
    const int rbase = warp_m * 64 + (lane >> 2);
    const int cbase = n0 + warp_n * 32 + 2 * (lane & 3);
#pragma unroll
    for (int mt = 0; mt < 4; mt++) {
#pragma unroll
        for (int half = 0; half < 2; half++) {  // row, row+8
            unsigned long long best = 0xFFFFFFFFFFFFFFFFull;
#pragma unroll
            for (int nt = 0; nt < 4; nt++) {
#pragma unroll
                for (int j = 0; j < 2; j++) {
                    int col = cbase + nt * 8 + j;
                    float s = wns[col - n0] - 2.f * c[mt][nt][half * 2 + j];
                    unsigned us = __float_as_uint(s);
                    us = (us & 0x80000000u) ? ~us : (us | 0x80000000u);
                    unsigned long long p = ((unsigned long long)us << 32) | (unsigned)col;
                    if (p < best) best = p;
                }
            }
#pragma unroll
            for (int off = 1; off < 4; off <<= 1) {
                unsigned long long o = __shfl_xor_sync(0xffffffffu, best, off);
                if (o < best) best = o;
            }
            if ((lane & 3) == 0) {
                int m = m0 + rbase + mt * 16 + half * 8;
                atomicMin(&g_best[m], best);
            }
        }
    }
}

// ---------------- K4: per-point gather / quantize / scatter EMA ----------------
__global__ void assign_kernel(const float* __restrict__ z, const float* __restrict__ w,
                              float* __restrict__ out_zq, float* __restrict__ out_idx,
                              float* __restrict__ out_ea) {
    int warp = (blockIdx.x * blockDim.x + threadIdx.x) >> 5;
    int lane = threadIdx.x & 31;
    if (warp >= NP) return;
    unsigned long long b = g_best[warp];
    int idx = (int)(unsigned)(b & 0xFFFFFFFFull);
    const float4* zp = (const float4*)(z + (size_t)warp * DIM);
    const float4* wp = (const float4*)(w + (size_t)idx * DIM);
    float4* oq = (float4*)(out_zq + (size_t)warp * DIM);
    float* ea = out_ea + (size_t)idx * DIM;
    float local = 0.f;
#pragma unroll
    for (int it = 0; it < 2; it++) {
        int v = lane + it * 32;
        float4 zv = zp[v];
        float4 wv = wp[v];
        float dx = wv.x - zv.x, dy = wv.y - zv.y, dz = wv.z - zv.z, dw = wv.w - zv.w;
        float4 o; o.x = zv.x + dx; o.y = zv.y + dy; o.z = zv.z + dz; o.w = zv.w + dw;
        oq[v] = o;
        local += dx * dx + dy * dy + dz * dz + dw * dw;
        int d = v * 4;
        atomicAdd(&ea[d + 0], OMDECAYF * zv.x);
        atomicAdd(&ea[d + 1], OMDECAYF * zv.y);
        atomicAdd(&ea[d + 2], OMDECAYF * zv.z);
        atomicAdd(&ea[d + 3], OMDECAYF * zv.w);
    }
#pragma unroll
    for (int off = 16; off; off >>= 1) local += __shfl_xor_sync(0xffffffffu, local, off);
    if (lane == 0) {
        g_ptloss[warp] = local;
        out_idx[warp] = (float)idx;
        atomicAdd(&g_counts[idx], 1.0f);
    }
}

// ---------------- K5a: new cluster size ----------------
__global__ void cs_kernel(const float* __restrict__ cs_in, float* __restrict__ out_cs) {
    int i = blockIdx.x * blockDim.x + threadIdx.x;
    if (i < NC) out_cs[i] = DECAYF * cs_in[i] + OMDECAYF * g_counts[i];
}

// ---------------- K5b: deterministic reductions (n, loss) ----------------
__global__ void reduce_kernel(const float* __restrict__ out_cs, float* __restrict__ out_loss) {
    __shared__ float sm[1024];
    int t = threadIdx.x;
    float s = 0.f;
    for (int i = t; i < NC; i += 1024) s += out_cs[i];
    sm[t] = s; __syncthreads();
    for (int off = 512; off; off >>= 1) { if (t < off) sm[t] += sm[t + off]; __syncthreads(); }
    if (t == 0) g_n = sm[0];
    __syncthreads();
    float l = 0.f;
    for (int i = t; i < NP; i += 1024) l += g_ptloss[i];
    sm[t] = l; __syncthreads();
    for (int off = 512; off; off >>= 1) { if (t < off) sm[t] += sm[t + off]; __syncthreads(); }
    if (t == 0) out_loss[0] = sm[0] * (1.f / (float)(NP * DIM));
}

// ---------------- K5c: new weight ----------------
__global__ void weight_kernel(const float* __restrict__ out_ea, const float* __restrict__ out_cs,
                              float* __restrict__ out_w) {
    int i = blockIdx.x * blockDim.x + threadIdx.x;
    if (i >= NC * DIM) return;
    int k = i >> 8;
    float n = g_n;
    float denom = (out_cs[k] + EPSF) / (n + (float)NC * EPSF) * n;
    out_w[i] = out_ea[i] / denom;
}

// ---------------- launch ----------------
extern "C" void kernel_launch(void* const* d_in, const int* in_sizes, int n_in,
                              void* d_out, int out_size) {
    const float* z  = (const float*)d_in[0];
    const float* w  = (const float*)d_in[1];
    const float* cs = (const float*)d_in[2];
    const float* ea = (const float*)d_in[3];
    float* out = (float*)d_out;
    float* out_zq   = out;
    float* out_loss = out + (size_t)NP * DIM;
    float* out_idx  = out_loss + 1;
    float* out_w    = out_idx + NP;
    float* out_cs   = out_w + (size_t)NC * DIM;
    float* out_ea   = out_cs + NC;

    constexpr int SMEM_GEMM = 1024 + STAGES * STAGE_B;   // 1024 + 122880 = 123904
    cudaFuncSetAttribute(mma_gemm_argmin, cudaFuncAttributeMaxDynamicSharedMemorySize, SMEM_GEMM);

    init_kernel<<<(NC * DIM + 1023) / 1024, 1024>>>(ea, out_ea);
    split_kernel<<<(NP * DIM + 1023) / 1024, 1024>>>(z, w);
    wnorm_kernel<<<NC * 32 / 256, 256>>>(w);
    dim3 g(NP / BM, NC / BN);
    mma_gemm_argmin<<<g, 256, SMEM_GEMM>>>();
    assign_kernel<<<NP * 32 / 256, 256>>>(z, w, out_zq, out_idx, out_ea);
    cs_kernel<<<(NC + 255) / 256, 256>>>(cs, out_cs);
    reduce_kernel<<<1, 1024>>>(out_cs, out_loss);
    weight_kernel<<<(NC * DIM + 1023) / 1024, 1024>>>(out_ea, out_cs, out_w);
}

// round 6
// speedup vs baseline: 1.1027x; 1.1027x over previous
#include <cuda_runtime.h>
#include <cuda_fp16.h>
#include <cstdint>

#define NP 16384      // number of z vectors (16*32*32)
#define NC 8192       // codebook size
#define DIM 256       // embedding dim
#define DECAYF 0.99f
#define OMDECAYF 0.01f
#define EPSF 1e-5f

// GEMM tiling
#define BM 128
#define BN 128
#define BK 32                  // halves per k-chunk
#define NCHUNK (DIM / BK)      // 8
#define STAGES 3
#define ROWB 80                // smem row stride in bytes (32 halves + 8 pad)
#define TILE_B (128 * ROWB)    // 10240 bytes per tile
#define STAGE_B (4 * TILE_B)   // A_hi, A_lo, B_hi, B_lo
#define NTHREADS 512           // 16 warps -> 4 per SMSP

// ---------------- scratch (no allocation allowed) ----------------
__device__ unsigned long long g_best[NP];   // packed (ordered_score<<32 | idx)
__device__ float g_wnorm[NC];
__device__ float g_counts[NC];
__device__ float g_ptloss[NP];
__device__ float g_n;
__device__ __align__(256) __half g_zh[NP * DIM];
__device__ __align__(256) __half g_zl[NP * DIM];
__device__ __align__(256) __half g_wh[NC * DIM];
__device__ __align__(256) __half g_wl[NC * DIM];

// ---------------- PTX helpers ----------------
__device__ __forceinline__ uint32_t smem_u32(const void* p) {
    uint32_t a;
    asm("{ .reg .u64 t; cvta.to.shared.u64 t, %1; cvt.u32.u64 %0, t; }" : "=r"(a) : "l"(p));
    return a;
}
__device__ __forceinline__ void cp16(uint32_t dst, const void* src) {
    asm volatile("cp.async.cg.shared.global [%0], [%1], 16;" :: "r"(dst), "l"(src) : "memory");
}
#define CP_COMMIT() asm volatile("cp.async.commit_group;" ::: "memory")
#define CP_WAIT1()  asm volatile("cp.async.wait_group 1;" ::: "memory")

__device__ __forceinline__ void ldm_x4(uint32_t* r, uint32_t addr) {
    asm volatile("ldmatrix.sync.aligned.m8n8.x4.shared.b16 {%0,%1,%2,%3}, [%4];"
        : "=r"(r[0]), "=r"(r[1]), "=r"(r[2]), "=r"(r[3]) : "r"(addr));
}
__device__ __forceinline__ void mma16816(float* c, const uint32_t* a, const uint32_t* b) {
    asm volatile(
        "mma.sync.aligned.m16n8k16.row.col.f32.f16.f16.f32 "
        "{%0,%1,%2,%3}, {%4,%5,%6,%7}, {%8,%9}, {%0,%1,%2,%3};"
        : "+f"(c[0]), "+f"(c[1]), "+f"(c[2]), "+f"(c[3])
        : "r"(a[0]), "r"(a[1]), "r"(a[2]), "r"(a[3]), "r"(b[0]), "r"(b[1]));
}

// ---------------- K0: init scratch + out_embed_avg = DECAY*embed_avg ----------------
__global__ void init_kernel(const float* __restrict__ ea_in, float* __restrict__ out_ea) {
    int i = blockIdx.x * blockDim.x + threadIdx.x;
    if (i < NP) g_best[i] = 0xFFFFFFFFFFFFFFFFull;
    if (i < NC) g_counts[i] = 0.f;
    if (i < NC * DIM) out_ea[i] = DECAYF * ea_in[i];
}

// ---------------- K1: fp16 hi/lo split of z and w ----------------
__global__ void split_kernel(const float* __restrict__ z, const float* __restrict__ w) {
    int i = blockIdx.x * blockDim.x + threadIdx.x;
    if (i < NP * DIM) {
        float x = z[i];
        __half h = __float2half_rn(x);
        g_zh[i] = h;
        g_zl[i] = __float2half_rn(x - __half2float(h));
    }
    if (i < NC * DIM) {
        float x = w[i];
        __half h = __float2half_rn(x);
        g_wh[i] = h;
        g_wl[i] = __float2half_rn(x - __half2float(h));
    }
}

// ---------------- K2: per-code squared norms (fp32 exact) ----------------
__global__ void wnorm_kernel(const float* __restrict__ w) {
    int warp = (blockIdx.x * blockDim.x + threadIdx.x) >> 5;
    int lane = threadIdx.x & 31;
    if (warp >= NC) return;
    const float4* row = (const float4*)(w + (size_t)warp * DIM);
    float s = 0.f;
#pragma unroll
    for (int it = 0; it < 2; it++) {
        float4 v = row[lane + it * 32];
        s += v.x * v.x + v.y * v.y + v.z * v.z + v.w * v.w;
    }
#pragma unroll
    for (int off = 16; off; off >>= 1) s += __shfl_xor_sync(0xffffffffu, s, off);
    if (lane == 0) g_wnorm[warp] = s;
}

// ---------------- K3: mma.sync fp16-split GEMM + fused argmin ----------------
// dot = zh*wh + zh*wl + zl*wh ; score = ||w||^2 - 2*dot
// 16 warps (4x4 grid, 32x32 warp tile) -> 4 warps/SMSP for latency hiding.
__global__ __launch_bounds__(NTHREADS, 1) void mma_gemm_argmin() {
    extern __shared__ char smem[];
    const uint32_t sb = smem_u32(smem);
    const int tid = threadIdx.x, wid = tid >> 5, lane = tid & 31;
    const int warp_m = wid >> 2, warp_n = wid & 3;   // 4 x 4 warps
    const int m0 = blockIdx.x * BM, n0 = blockIdx.y * BN;

    constexpr uint32_t OFF_STAGE = 1024;

    // wnorm tile
    float* wns = (float*)smem;
    if (tid < BN) wns[tid] = g_wnorm[n0 + tid];

    // ---- cp.async stage loader (2048 vec16 loads / 512 threads = 4 iters) ----
    auto load_stage = [&](int chunk, int stg) {
        const uint32_t stage = sb + OFF_STAGE + stg * STAGE_B;
#pragma unroll
        for (int r = 0; r < 4; r++) {
            int idx = tid + r * NTHREADS;      // 0..2047
            int tile = idx >> 9;               // 0..3
            int q = idx & 511;
            int row = q >> 2, cj = q & 3;
            const __half* src;
            if (tile == 0)      src = g_zh + (size_t)(m0 + row) * DIM;
            else if (tile == 1) src = g_zl + (size_t)(m0 + row) * DIM;
            else if (tile == 2) src = g_wh + (size_t)(n0 + row) * DIM;
            else                src = g_wl + (size_t)(n0 + row) * DIM;
            src += chunk * BK + cj * 8;
            cp16(stage + tile * TILE_B + row * ROWB + cj * 16, src);
        }
    };

    load_stage(0, 0); CP_COMMIT();
    load_stage(1, 1); CP_COMMIT();

    float c[2][4][4] = {};    // [mt][nt][4]  (32x32 warp tile)

    for (int ch = 0; ch < NCHUNK; ch++) {
        CP_WAIT1();
        __syncthreads();
        if (ch + 2 < NCHUNK) load_stage(ch + 2, (ch + 2) % STAGES);
        CP_COMMIT();

        const uint32_t stage = sb + OFF_STAGE + (ch % STAGES) * STAGE_B;
        const uint32_t sAh = stage;
        const uint32_t sAl = stage + TILE_B;
        const uint32_t sBh = stage + 2 * TILE_B;
        const uint32_t sBl = stage + 3 * TILE_B;

#pragma unroll
        for (int s = 0; s < 2; s++) {          // two k16 steps per chunk
            const uint32_t acol = s * 32 + ((lane >> 4) << 4);
            const int arow = lane & 15;
            uint32_t ah[2][4], al[2][4];
#pragma unroll
            for (int mt = 0; mt < 2; mt++) {
                uint32_t off = (uint32_t)(warp_m * 32 + mt * 16 + arow) * ROWB + acol;
                ldm_x4(ah[mt], sAh + off);
                ldm_x4(al[mt], sAl + off);
            }
            const int brow = ((lane >> 4) << 3) + (lane & 7);
            const uint32_t bcol = s * 32 + ((lane >> 3) & 1) * 16;
            uint32_t bh[2][4], bl[2][4];
#pragma unroll
            for (int nt2 = 0; nt2 < 2; nt2++) {
                uint32_t off = (uint32_t)(warp_n * 32 + nt2 * 16 + brow) * ROWB + bcol;
                ldm_x4(bh[nt2], sBh + off);
                ldm_x4(bl[nt2], sBl + off);
            }
#pragma unroll
            for (int mt = 0; mt < 2; mt++)
#pragma unroll
                for (int nt = 0; nt < 4; nt++)
                    mma16816(c[mt][nt], ah[mt], &bh[nt >> 1][(nt & 1) * 2]);
#pragma unroll
            for (int mt = 0; mt < 2; mt++)
#pragma unroll
                for (int nt = 0; nt < 4; nt++)
                    mma16816(c[mt][nt], ah[mt], &bl[nt >> 1][(nt & 1) * 2]);
#pragma unroll
            for (int mt = 0; mt < 2; mt++)
#pragma unroll
                for (int nt = 0; nt < 4; nt++)
                    mma16816(c[mt][nt], al[mt], &bh[nt >> 1][(nt & 1) * 2]);
        }
    }

    // ---- epilogue: fused argmin ----
    const int rbase = warp_m * 32 + (lane >> 2);
    const int cbase = n0 + warp_n * 32 + 2 * (lane & 3);
#pragma unroll
    for (int mt = 0; mt < 2; mt++) {
#pragma unroll
        for (int half = 0; half < 2; half++) {  // row, row+8
            unsigned long long best = 0xFFFFFFFFFFFFFFFFull;
#pragma unroll
            for (int nt = 0; nt < 4; nt++) {
#pragma unroll
                for (int j = 0; j < 2; j++) {
                    int col = cbase + nt * 8 + j;
                    float s = wns[col - n0] - 2.f * c[mt][nt][half * 2 + j];
                    unsigned us = __float_as_uint(s);
                    us = (us & 0x80000000u) ? ~us : (us | 0x80000000u);
                    unsigned long long p = ((unsigned long long)us << 32) | (unsigned)col;
                    if (p < best) best = p;
                }
            }
#pragma unroll
            for (int off = 1; off < 4; off <<= 1) {
                unsigned long long o = __shfl_xor_sync(0xffffffffu, best, off);
                if (o < best) best = o;
            }
            if ((lane & 3) == 0) {
                int m = m0 + rbase + mt * 16 + half * 8;
                atomicMin(&g_best[m], best);
            }
        }
    }
}

// ---------------- K4: per-point gather / quantize / scatter EMA ----------------
__global__ void assign_kernel(const float* __restrict__ z, const float* __restrict__ w,
                              float* __restrict__ out_zq, float* __restrict__ out_idx,
                              float* __restrict__ out_ea) {
    int warp = (blockIdx.x * blockDim.x + threadIdx.x) >> 5;
    int lane = threadIdx.x & 31;
    if (warp >= NP) return;
    unsigned long long b = g_best[warp];
    int idx = (int)(unsigned)(b & 0xFFFFFFFFull);
    const float4* zp = (const float4*)(z + (size_t)warp * DIM);
    const float4* wp = (const float4*)(w + (size_t)idx * DIM);
    float4* oq = (float4*)(out_zq + (size_t)warp * DIM);
    float* ea = out_ea + (size_t)idx * DIM;
    float local = 0.f;
#pragma unroll
    for (int it = 0; it < 2; it++) {
        int v = lane + it * 32;
        float4 zv = zp[v];
        float4 wv = wp[v];
        float dx = wv.x - zv.x, dy = wv.y - zv.y, dz = wv.z - zv.z, dw = wv.w - zv.w;
        float4 o; o.x = zv.x + dx; o.y = zv.y + dy; o.z = zv.z + dz; o.w = zv.w + dw;
        oq[v] = o;
        local += dx * dx + dy * dy + dz * dz + dw * dw;
        int d = v * 4;
        atomicAdd(&ea[d + 0], OMDECAYF * zv.x);
        atomicAdd(&ea[d + 1], OMDECAYF * zv.y);
        atomicAdd(&ea[d + 2], OMDECAYF * zv.z);
        atomicAdd(&ea[d + 3], OMDECAYF * zv.w);
    }
#pragma unroll
    for (int off = 16; off; off >>= 1) local += __shfl_xor_sync(0xffffffffu, local, off);
    if (lane == 0) {
        g_ptloss[warp] = local;
        out_idx[warp] = (float)idx;
        atomicAdd(&g_counts[idx], 1.0f);
    }
}

// ---------------- K5a: new cluster size ----------------
__global__ void cs_kernel(const float* __restrict__ cs_in, float* __restrict__ out_cs) {
    int i = blockIdx.x * blockDim.x + threadIdx.x;
    if (i < NC) out_cs[i] = DECAYF * cs_in[i] + OMDECAYF * g_counts[i];
}

// ---------------- K5b: deterministic reductions (n, loss) ----------------
__global__ void reduce_kernel(const float* __restrict__ out_cs, float* __restrict__ out_loss) {
    __shared__ float sm[1024];
    int t = threadIdx.x;
    float s = 0.f;
    for (int i = t; i < NC; i += 1024) s += out_cs[i];
    sm[t] = s; __syncthreads();
    for (int off = 512; off; off >>= 1) { if (t < off) sm[t] += sm[t + off]; __syncthreads(); }
    if (t == 0) g_n = sm[0];
    __syncthreads();
    float l = 0.f;
    for (int i = t; i < NP; i += 1024) l += g_ptloss[i];
    sm[t] = l; __syncthreads();
    for (int off = 512; off; off >>= 1) { if (t < off) sm[t] += sm[t + off]; __syncthreads(); }
    if (t == 0) out_loss[0] = sm[0] * (1.f / (float)(NP * DIM));
}

// ---------------- K5c: new weight ----------------
__global__ void weight_kernel(const float* __restrict__ out_ea, const float* __restrict__ out_cs,
                              float* __restrict__ out_w) {
    int i = blockIdx.x * blockDim.x + threadIdx.x;
    if (i >= NC * DIM) return;
    int k = i >> 8;
    float n = g_n;
    float denom = (out_cs[k] + EPSF) / (n + (float)NC * EPSF) * n;
    out_w[i] = out_ea[i] / denom;
}

// ---------------- launch ----------------
extern "C" void kernel_launch(void* const* d_in, const int* in_sizes, int n_in,
                              void* d_out, int out_size) {
    const float* z  = (const float*)d_in[0];
    const float* w  = (const float*)d_in[1];
    const float* cs = (const float*)d_in[2];
    const float* ea = (const float*)d_in[3];
    float* out = (float*)d_out;
    float* out_zq   = out;
    float* out_loss = out + (size_t)NP * DIM;
    float* out_idx  = out_loss + 1;
    float* out_w    = out_idx + NP;
    float* out_cs   = out_w + (size_t)NC * DIM;
    float* out_ea   = out_cs + NC;

    constexpr int SMEM_GEMM = 1024 + STAGES * STAGE_B;   // 1024 + 122880 = 123904
    cudaFuncSetAttribute(mma_gemm_argmin, cudaFuncAttributeMaxDynamicSharedMemorySize, SMEM_GEMM);

    init_kernel<<<(NC * DIM + 1023) / 1024, 1024>>>(ea, out_ea);
    split_kernel<<<(NP * DIM + 1023) / 1024, 1024>>>(z, w);
    wnorm_kernel<<<NC * 32 / 256, 256>>>(w);
    dim3 g(NP / BM, NC / BN);
    mma_gemm_argmin<<<g, NTHREADS, SMEM_GEMM>>>();
    assign_kernel<<<NP * 32 / 256, 256>>>(z, w, out_zq, out_idx, out_ea);
    cs_kernel<<<(NC + 255) / 256, 256>>>(cs, out_cs);
    reduce_kernel<<<1, 1024>>>(out_cs, out_loss);
    weight_kernel<<<(NC * DIM + 1023) / 1024, 1024>>>(out_ea, out_cs, out_w);
}